// round 3
// baseline (speedup 1.0000x reference)
#include <cuda_runtime.h>
#include <math.h>

// ---------------------------------------------------------------------------
// TCCLModel — full pipeline on GB300, fp32, multi-kernel (BN batch stats need
// global syncs). All scratch in __device__ globals (no allocation anywhere).
// ---------------------------------------------------------------------------

#define EPS_BN   1e-5f
#define EPS_NORM 1e-12f

// dims
#define BB   256
#define LL   8192

// scratch (per stream: 0 = x1 path, 1 = x2 path)
// pooled raw conv outputs stored as (max,min) pairs: layout [b][c][wp][2]
static __device__ float g_c1[2][16777216];  // 256*16*2048*2
static __device__ float g_c2[2][8388608];   // 256*32*512*2
static __device__ float g_c3[2][4194304];   // 256*64*128*2
static __device__ float g_h [2][2097152];   // 256*64*128  (encoder output h)
static __device__ float g_t1[2][2097152];   // tconv1 raw
static __device__ float g_t2[2][2097152];   // tconv2 raw
static __device__ float g_S [2][81920];     // 256*64*5 window sums of normalized h
static __device__ float g_kc[2][81920];     // 256*64*5 centered+normalized k
static __device__ float g_ka[2][81920];     // 256*320 flat-normalized k
static __device__ float g_sum[2*5*64];      // BN sums   [stream][stage][ch]
static __device__ float g_sq [2*5*64];      // BN sumsqs
static __device__ float g_aff[2*5*64*2];    // BN affine (a,b) per channel
static __device__ float g_sim[3][65536];    // three 256x256 similarity matrices
static __device__ float g_row[3*256];       // per-row infonce terms

// ---------------------------------------------------------------------------
// reductions
// ---------------------------------------------------------------------------
static __device__ __forceinline__ float warpReduceSum(float v) {
    #pragma unroll
    for (int o = 16; o > 0; o >>= 1) v += __shfl_xor_sync(0xffffffffu, v, o);
    return v;
}
static __device__ __forceinline__ float warpReduceMax(float v) {
    #pragma unroll
    for (int o = 16; o > 0; o >>= 1) v = fmaxf(v, __shfl_xor_sync(0xffffffffu, v, o));
    return v;
}
static __device__ __forceinline__ float blockReduceSum(float v, float* scr, int nw) {
    int tid = threadIdx.x;
    v = warpReduceSum(v);
    if ((tid & 31) == 0) scr[tid >> 5] = v;
    __syncthreads();
    float r = 0.f;
    for (int i = 0; i < nw; i++) r += scr[i];
    __syncthreads();
    return r;
}
static __device__ __forceinline__ float blockReduceMax(float v, float* scr, int nw) {
    int tid = threadIdx.x;
    v = warpReduceMax(v);
    if ((tid & 31) == 0) scr[tid >> 5] = v;
    __syncthreads();
    float r = -3.4e38f;
    for (int i = 0; i < nw; i++) r = fmaxf(r, scr[i]);
    __syncthreads();
    return r;
}

// ---------------------------------------------------------------------------
// generic fused conv1d('same') + raw-stat accumulation (+ optional pooled
// min/max output).  INMODE: 0 = raw input, 1 = (max,min)+affine+relu,
// 2 = raw+affine+relu.  POOL: write (max,min) over aligned 4-windows.
// Per-thread register blocking: CACC=8 channels x TP positions.
// ---------------------------------------------------------------------------
template<int CIN,int COUT,int KW,int W,int COG,int NT,int TP,int INMODE,bool POOL>
__global__ void __launch_bounds__(NT) conv_bn_kernel(
    const float* __restrict__ in0, const float* __restrict__ in1,
    const float* __restrict__ wt,  const float* __restrict__ bias,
    float* __restrict__ out0, float* __restrict__ out1,
    const float* __restrict__ aff0, const float* __restrict__ aff1,
    float* __restrict__ sum0, float* __restrict__ sum1,
    float* __restrict__ sq0,  float* __restrict__ sq1)
{
    constexpr int TILE = NT * TP;
    constexpr int PAD  = (KW - 1) / 2;
    constexpr int XROW = TILE + KW - 1;
    constexpr int NCG  = COUT / COG;
    constexpr int CACC = 8;
    static_assert(COG % CACC == 0, "");
    static_assert(!POOL || TP == 4, "");

    extern __shared__ float sh[];
    float* sx   = sh;                       // CIN*XROW activated input tile
    float* sw   = sx + CIN * XROW;          // COG*CIN*KW weights
    float* sb   = sw + COG * CIN * KW;      // COG bias
    float* ssum = sb + COG;                 // COG block-partial sums
    float* ssq  = ssum + COG;               // COG block-partial sumsqs

    const int z      = blockIdx.z;
    const int stream = z / NCG;
    const int cg     = z - stream * NCG;
    const float* __restrict__ in  = stream ? in1  : in0;
    float*       __restrict__ out = stream ? out1 : out0;
    const float* __restrict__ af  = stream ? aff1 : aff0;
    float* gsum = stream ? sum1 : sum0;
    float* gsq  = stream ? sq1  : sq0;
    const int b     = blockIdx.y;
    const int tbase = blockIdx.x * TILE;
    const int tid   = threadIdx.x;

    for (int i = tid; i < COG; i += NT) { sb[i] = bias[cg*COG + i]; ssum[i] = 0.f; ssq[i] = 0.f; }
    for (int i = tid; i < COG*CIN*KW; i += NT) {
        int co = i / (CIN*KW);
        int r  = i - co*(CIN*KW);
        sw[i] = wt[(cg*COG + co)*(CIN*KW) + r];
    }
    for (int i = tid; i < CIN*XROW; i += NT) {
        int ci = i / XROW;
        int p  = i - ci*XROW;
        int g  = tbase - PAD + p;
        float v = 0.f;
        if (g >= 0 && g < W) {
            if constexpr (INMODE == 0) {
                v = in[(b*CIN + ci)*W + g];
            } else if constexpr (INMODE == 1) {
                float a = af[ci*2+0], bb = af[ci*2+1];
                float2 mm = ((const float2*)in)[(b*CIN + ci)*W + g];
                v = fmaxf(fmaxf(fmaf(a, mm.x, bb), fmaf(a, mm.y, bb)), 0.f);
            } else {
                float a = af[ci*2+0], bb = af[ci*2+1];
                v = fmaxf(fmaf(a, in[(b*CIN + ci)*W + g], bb), 0.f);
            }
        }
        sx[i] = v;
    }
    __syncthreads();

    const int x0   = tid * TP;
    const int lane = tid & 31;

    #pragma unroll 1
    for (int ch = 0; ch < COG; ch += CACC) {
        float acc[CACC][TP];
        #pragma unroll
        for (int c = 0; c < CACC; c++)
            #pragma unroll
            for (int p = 0; p < TP; p++) acc[c][p] = sb[ch + c];

        #pragma unroll 1
        for (int ci = 0; ci < CIN; ci++) {
            float xv[TP + KW - 1];
            const float* sxr = sx + ci*XROW + x0;
            #pragma unroll
            for (int i2 = 0; i2 < TP + KW - 1; i2++) xv[i2] = sxr[i2];
            #pragma unroll
            for (int k = 0; k < KW; k++) {
                #pragma unroll
                for (int c = 0; c < CACC; c++) {
                    float wv = sw[((ch + c)*CIN + ci)*KW + k];
                    #pragma unroll
                    for (int p = 0; p < TP; p++)
                        acc[c][p] = fmaf(xv[k + p], wv, acc[c][p]);
                }
            }
        }

        #pragma unroll
        for (int c = 0; c < CACC; c++) {
            float s = 0.f, s2 = 0.f;
            float mx = -3.4e38f, mn = 3.4e38f;
            #pragma unroll
            for (int p = 0; p < TP; p++) {
                float v = acc[c][p];
                s += v; s2 = fmaf(v, v, s2);
                mx = fmaxf(mx, v); mn = fminf(mn, v);
            }
            float rs = warpReduceSum(s);
            float rq = warpReduceSum(s2);
            if (lane == 0) { atomicAdd(&ssum[ch + c], rs); atomicAdd(&ssq[ch + c], rq); }
            const int coG = cg*COG + ch + c;
            if constexpr (POOL) {
                ((float2*)out)[(b*COUT + coG)*(W/4) + (tbase >> 2) + tid] = make_float2(mx, mn);
            } else {
                #pragma unroll
                for (int p = 0; p < TP; p++)
                    out[(b*COUT + coG)*W + tbase + x0 + p] = acc[c][p];
            }
        }
    }
    __syncthreads();
    for (int i = tid; i < COG; i += NT) {
        atomicAdd(&gsum[cg*COG + i], ssum[i]);
        atomicAdd(&gsq[cg*COG + i], ssq[i]);
    }
}

// ---------------------------------------------------------------------------
// small kernels
// ---------------------------------------------------------------------------
__global__ void zero_stats_kernel() {
    int i = blockIdx.x * blockDim.x + threadIdx.x;
    if (i < 2*5*64) { g_sum[i] = 0.f; g_sq[i] = 0.f; }
}

__global__ void finalize_bn_kernel(const float* __restrict__ gamma,
                                   const float* __restrict__ beta,
                                   int C, float invN, int stage) {
    int z = blockIdx.x; int c = threadIdx.x;
    if (c < C) {
        float s = g_sum[(z*5 + stage)*64 + c];
        float q = g_sq [(z*5 + stage)*64 + c];
        float mean = s * invN;
        float var  = fmaf(-mean, mean, q * invN);
        float a    = gamma[c] * rsqrtf(var + EPS_BN);
        float bb   = beta[c] - a * mean;
        g_aff[((z*5 + stage)*64 + c)*2 + 0] = a;
        g_aff[((z*5 + stage)*64 + c)*2 + 1] = bb;
    }
}

// h = relu(affine(stage2 pooled minmax))
__global__ void hcompute_kernel() {
    int z = blockIdx.y;
    int idx = blockIdx.x * blockDim.x + threadIdx.x;   // < 2097152
    const float* af = &g_aff[(z*5 + 2)*128];
    int c = (idx >> 7) & 63;
    float a = af[c*2], bb = af[c*2+1];
    float2 mm = ((const float2*)g_c3[z])[idx];
    g_h[z][idx] = fmaxf(fmaxf(fmaf(a, mm.x, bb), fmaf(a, mm.y, bb)), 0.f);
}

// per (stream,b,c): center+l2norm h row, emit 5 window sums S
__global__ void sprep_kernel() {
    int c = blockIdx.x, b = blockIdx.y, z = blockIdx.z;
    int t = threadIdx.x;                 // 128 threads
    __shared__ float scr[4];
    __shared__ float sedge[4];
    float v = g_h[z][(b*64 + c)*128 + t];
    float sum  = blockReduceSum(v, scr, 4);
    float mean = sum * (1.f/128.f);
    float e = v - mean;
    float q  = blockReduceSum(e*e, scr, 4);
    float se = blockReduceSum(e,   scr, 4);
    float inv = 1.f / fmaxf(sqrtf(q), EPS_NORM);
    float eh = e * inv;
    if (t == 0)   sedge[0] = eh;
    if (t == 1)   sedge[1] = eh;
    if (t == 126) sedge[2] = eh;
    if (t == 127) sedge[3] = eh;
    __syncthreads();
    if (t == 0) {
        float T = se * inv;
        float* o = &g_S[z][(b*64 + c)*5];
        o[0] = T - sedge[2] - sedge[3];
        o[1] = T - sedge[3];
        o[2] = T;
        o[3] = T - sedge[0];
        o[4] = T - sedge[0] - sedge[1];
    }
}

// per (stream,b): activate t2 raw (stage4 affine), adaptive-pool to 5 bins,
// emit flat-normalized k (320) and per-channel centered+normalized k (64x5).
__global__ void kcompute_kernel() {
    int b = blockIdx.x, z = blockIdx.y;
    int c = threadIdx.x;                 // 64 threads
    __shared__ float scr[2];
    const float* af = &g_aff[(z*5 + 4)*128];
    float a = af[c*2], bb = af[c*2+1];
    const float* row = &g_t2[z][(b*64 + c)*128];
    const int s0[5] = {0, 25, 51, 76, 102};
    const int e0[5] = {26, 52, 77, 103, 128};
    float kk[5];
    float local = 0.f;
    #pragma unroll
    for (int i = 0; i < 5; i++) {
        float s = 0.f;
        for (int w = s0[i]; w < e0[i]; w++)
            s += fmaxf(fmaf(a, row[w], bb), 0.f);
        kk[i] = s / (float)(e0[i] - s0[i]);
        local = fmaf(kk[i], kk[i], local);
    }
    float tot = blockReduceSum(local, scr, 2);
    float invf = 1.f / fmaxf(sqrtf(tot), EPS_NORM);
    float mu = (kk[0]+kk[1]+kk[2]+kk[3]+kk[4]) * 0.2f;
    float nn2 = 0.f;
    float d[5];
    #pragma unroll
    for (int i = 0; i < 5; i++) { d[i] = kk[i] - mu; nn2 = fmaf(d[i], d[i], nn2); }
    float invc = 1.f / fmaxf(sqrtf(nn2), EPS_NORM);
    #pragma unroll
    for (int i = 0; i < 5; i++) {
        g_ka[z][b*320 + c*5 + i]      = kk[i] * invf;
        g_kc[z][(b*64 + c)*5 + i]     = d[i] * invc;
    }
}

// three 256x256x320 GEMMs (A·B^T)
__global__ void matmul_kernel() {
    int m = blockIdx.z;
    const float* A; const float* Bm; float scale;
    if (m == 0)      { A = g_kc[0]; Bm = g_S[1];  scale = 1.f/128.f; }
    else if (m == 1) { A = g_kc[1]; Bm = g_S[0];  scale = 1.f/128.f; }
    else             { A = g_ka[0]; Bm = g_ka[1]; scale = 1.f; }
    __shared__ float As[16][33], Bs[16][33];
    int tx = threadIdx.x, ty = threadIdx.y;
    int i0 = blockIdx.x * 16, j0 = blockIdx.y * 16;
    float acc = 0.f;
    for (int kk = 0; kk < 320; kk += 32) {
        As[ty][tx]      = A [(i0+ty)*320 + kk + tx];
        As[ty][tx+16]   = A [(i0+ty)*320 + kk + tx + 16];
        Bs[ty][tx]      = Bm[(j0+ty)*320 + kk + tx];
        Bs[ty][tx+16]   = Bm[(j0+ty)*320 + kk + tx + 16];
        __syncthreads();
        #pragma unroll
        for (int k2 = 0; k2 < 32; k2++)
            acc = fmaf(As[ty][k2], Bs[tx][k2], acc);
        __syncthreads();
    }
    g_sim[m][(i0+ty)*256 + j0 + tx] = acc * scale;
}

// per-row infonce: logp diag = x_ii - logsumexp_j(x_ij), x = sim/T
__global__ void rows_kernel() {
    int i = blockIdx.x, m = blockIdx.y;
    int j = threadIdx.x;                 // 256
    __shared__ float scr[8];
    __shared__ float sdiag;
    float x = g_sim[m][i*256 + j] * 10.0f;     // 1/TEMPERATURE
    if (j == i) sdiag = x;
    float mx = blockReduceMax(x, scr, 8);
    float e  = expf(x - mx);
    float tot = blockReduceSum(e, scr, 8);
    if (j == 0) g_row[m*256 + i] = sdiag - (mx + logf(tot));
}

__global__ void final_kernel(float* out) {
    int t = threadIdx.x;                 // 256
    __shared__ float scr[8];
    float sA = blockReduceSum(g_row[0*256 + t], scr, 8);
    float sB = blockReduceSum(g_row[1*256 + t], scr, 8);
    float sC = blockReduceSum(g_row[2*256 + t], scr, 8);
    if (t == 0) {
        float mA = sA * (1.f/256.f);
        float mB = sB * (1.f/256.f);
        float mC = sC * (1.f/256.f);
        // loss_matching = (-mA + -mB)/2 ; loss_template = -mC
        out[0] = (-mA - mB) * 0.5f + 0.5f * (-mC);
    }
}

// ---------------------------------------------------------------------------
// host
// ---------------------------------------------------------------------------
extern "C" void kernel_launch(void* const* d_in, const int* in_sizes, int n_in,
                              void* d_out, int out_size) {
    (void)in_sizes; (void)n_in; (void)out_size;
    const float* x1  = (const float*)d_in[0];
    const float* x2  = (const float*)d_in[1];
    const float* w1  = (const float*)d_in[2];
    const float* b1  = (const float*)d_in[3];
    const float* g1  = (const float*)d_in[4];
    const float* be1 = (const float*)d_in[5];
    const float* w2  = (const float*)d_in[6];
    const float* b2  = (const float*)d_in[7];
    const float* g2  = (const float*)d_in[8];
    const float* be2 = (const float*)d_in[9];
    const float* w3  = (const float*)d_in[10];
    const float* b3  = (const float*)d_in[11];
    const float* g3  = (const float*)d_in[12];
    const float* be3 = (const float*)d_in[13];
    const float* tw1 = (const float*)d_in[14];
    const float* tb1 = (const float*)d_in[15];
    const float* tg1 = (const float*)d_in[16];
    const float* tbe1= (const float*)d_in[17];
    const float* tw2 = (const float*)d_in[18];
    const float* tb2 = (const float*)d_in[19];
    const float* tg2 = (const float*)d_in[20];
    const float* tbe2= (const float*)d_in[21];

    float *pc1, *pc2, *pc3, *ph, *pt1, *pt2, *psum, *psq, *paff;
    cudaGetSymbolAddress((void**)&pc1, g_c1);
    cudaGetSymbolAddress((void**)&pc2, g_c2);
    cudaGetSymbolAddress((void**)&pc3, g_c3);
    cudaGetSymbolAddress((void**)&ph,  g_h);
    cudaGetSymbolAddress((void**)&pt1, g_t1);
    cudaGetSymbolAddress((void**)&pt2, g_t2);
    cudaGetSymbolAddress((void**)&psum, g_sum);
    cudaGetSymbolAddress((void**)&psq,  g_sq);
    cudaGetSymbolAddress((void**)&paff, g_aff);

    const int S_C1 = 16777216, S_C2 = 8388608, S_C3 = 4194304, S_H = 2097152;
    auto SUMP = [&](int z, int st) { return psum + (z*5 + st)*64; };
    auto SQP  = [&](int z, int st) { return psq  + (z*5 + st)*64; };
    auto AFFP = [&](int z, int st) { return paff + (z*5 + st)*128; };

    auto kc1 = conv_bn_kernel<1, 16, 17, 8192, 16, 256, 4, 0, true >;
    auto kc2 = conv_bn_kernel<16,32, 17, 2048, 32, 128, 4, 1, true >;
    auto kc3 = conv_bn_kernel<32,64, 17, 512,  16, 128, 4, 1, true >;
    auto kt1 = conv_bn_kernel<64,64, 5,  128,  16, 128, 1, 0, false>;
    auto kt2 = conv_bn_kernel<64,64, 3,  128,  16, 128, 1, 2, false>;

    const int sm_c1 = (1*1040  + 16*1*17  + 3*16)*4;   // 5440
    const int sm_c2 = (16*528  + 32*16*17 + 3*32)*4;   // 68992
    const int sm_c3 = (32*528  + 16*32*17 + 3*16)*4;   // 102592
    const int sm_t1 = (64*132  + 16*64*5  + 3*16)*4;   // 54464
    const int sm_t2 = (64*130  + 16*64*3  + 3*16)*4;   // 45760

    cudaFuncSetAttribute((const void*)kc2, cudaFuncAttributeMaxDynamicSharedMemorySize, sm_c2);
    cudaFuncSetAttribute((const void*)kc3, cudaFuncAttributeMaxDynamicSharedMemorySize, sm_c3);
    cudaFuncSetAttribute((const void*)kt1, cudaFuncAttributeMaxDynamicSharedMemorySize, sm_t1);

    zero_stats_kernel<<<3, 256>>>();

    // stage 0: conv1 + stats + pooled minmax
    kc1<<<dim3(8, BB, 2), 256, sm_c1>>>(x1, x2, w1, b1,
        pc1, pc1 + S_C1, nullptr, nullptr,
        SUMP(0,0), SUMP(1,0), SQP(0,0), SQP(1,0));
    finalize_bn_kernel<<<2, 64>>>(g1, be1, 16, 1.f/(256.f*8192.f), 0);

    // stage 1: conv2
    kc2<<<dim3(4, BB, 2), 128, sm_c2>>>(pc1, pc1 + S_C1, w2, b2,
        pc2, pc2 + S_C2, AFFP(0,0), AFFP(1,0),
        SUMP(0,1), SUMP(1,1), SQP(0,1), SQP(1,1));
    finalize_bn_kernel<<<2, 64>>>(g2, be2, 32, 1.f/(256.f*2048.f), 1);

    // stage 2: conv3 (4 cogroups per stream)
    kc3<<<dim3(1, BB, 8), 128, sm_c3>>>(pc2, pc2 + S_C2, w3, b3,
        pc3, pc3 + S_C3, AFFP(0,1), AFFP(1,1),
        SUMP(0,2), SUMP(1,2), SQP(0,2), SQP(1,2));
    finalize_bn_kernel<<<2, 64>>>(g3, be3, 64, 1.f/(256.f*512.f), 2);

    // encoder output h
    hcompute_kernel<<<dim3(8192, 2), 256>>>();

    // template head conv1 (input = h, raw)
    kt1<<<dim3(1, BB, 8), 128, sm_t1>>>(ph, ph + S_H, tw1, tb1,
        pt1, pt1 + S_H, nullptr, nullptr,
        SUMP(0,3), SUMP(1,3), SQP(0,3), SQP(1,3));
    finalize_bn_kernel<<<2, 64>>>(tg1, tbe1, 64, 1.f/(256.f*128.f), 3);

    // template head conv2 (input = t1 raw + stage3 affine + relu)
    kt2<<<dim3(1, BB, 8), 128, sm_t2>>>(pt1, pt1 + S_H, tw2, tb2,
        pt2, pt2 + S_H, AFFP(0,3), AFFP(1,3),
        SUMP(0,4), SUMP(1,4), SQP(0,4), SQP(1,4));
    finalize_bn_kernel<<<2, 64>>>(tg2, tbe2, 64, 1.f/(256.f*128.f), 4);

    // heads + similarity + losses
    kcompute_kernel<<<dim3(256, 2), 64>>>();
    sprep_kernel<<<dim3(64, 256, 2), 128>>>();
    matmul_kernel<<<dim3(16, 16, 3), dim3(16, 16)>>>();
    rows_kernel<<<dim3(256, 3), 256>>>();
    final_kernel<<<1, 256>>>((float*)d_out);
}

// round 5
// speedup vs baseline: 1.0880x; 1.0880x over previous
#include <cuda_runtime.h>
#include <math.h>

// ---------------------------------------------------------------------------
// TCCLModel — full pipeline on GB300, fp32, multi-kernel (BN batch stats need
// global syncs). All scratch in __device__ globals (no allocation anywhere).
// R4: float4-vectorized smem operand streams in conv_bn_kernel (padded weight
// stride KWP, LDS.128 for weights + input windows), kt1/kt2 switched to TP=2.
// ---------------------------------------------------------------------------

#define EPS_BN   1e-5f
#define EPS_NORM 1e-12f

// dims
#define BB   256
#define LL   8192

// scratch (per stream: 0 = x1 path, 1 = x2 path)
// pooled raw conv outputs stored as (max,min) pairs: layout [b][c][wp][2]
static __device__ float g_c1[2][16777216];  // 256*16*2048*2
static __device__ float g_c2[2][8388608];   // 256*32*512*2
static __device__ float g_c3[2][4194304];   // 256*64*128*2
static __device__ float g_h [2][2097152];   // 256*64*128  (encoder output h)
static __device__ float g_t1[2][2097152];   // tconv1 raw
static __device__ float g_t2[2][2097152];   // tconv2 raw
static __device__ float g_S [2][81920];     // 256*64*5 window sums of normalized h
static __device__ float g_kc[2][81920];     // 256*64*5 centered+normalized k
static __device__ float g_ka[2][81920];     // 256*320 flat-normalized k
static __device__ float g_sum[2*5*64];      // BN sums   [stream][stage][ch]
static __device__ float g_sq [2*5*64];      // BN sumsqs
static __device__ float g_aff[2*5*64*2];    // BN affine (a,b) per channel
static __device__ float g_sim[3][65536];    // three 256x256 similarity matrices
static __device__ float g_row[3*256];       // per-row infonce terms

// ---------------------------------------------------------------------------
// reductions
// ---------------------------------------------------------------------------
static __device__ __forceinline__ float warpReduceSum(float v) {
    #pragma unroll
    for (int o = 16; o > 0; o >>= 1) v += __shfl_xor_sync(0xffffffffu, v, o);
    return v;
}
static __device__ __forceinline__ float warpReduceMax(float v) {
    #pragma unroll
    for (int o = 16; o > 0; o >>= 1) v = fmaxf(v, __shfl_xor_sync(0xffffffffu, v, o));
    return v;
}
static __device__ __forceinline__ float blockReduceSum(float v, float* scr, int nw) {
    int tid = threadIdx.x;
    v = warpReduceSum(v);
    if ((tid & 31) == 0) scr[tid >> 5] = v;
    __syncthreads();
    float r = 0.f;
    for (int i = 0; i < nw; i++) r += scr[i];
    __syncthreads();
    return r;
}
static __device__ __forceinline__ float blockReduceMax(float v, float* scr, int nw) {
    int tid = threadIdx.x;
    v = warpReduceMax(v);
    if ((tid & 31) == 0) scr[tid >> 5] = v;
    __syncthreads();
    float r = -3.4e38f;
    for (int i = 0; i < nw; i++) r = fmaxf(r, scr[i]);
    __syncthreads();
    return r;
}

// ---------------------------------------------------------------------------
// generic fused conv1d('same') + raw-stat accumulation (+ optional pooled
// min/max output).  INMODE: 0 = raw input, 1 = (max,min)+affine+relu,
// 2 = raw+affine+relu.  POOL: write (max,min) over aligned 4-windows.
// Per-thread register blocking: CACC=8 channels x TP positions.
// Weights kept in smem at padded stride KWP (16B aligned rows) -> LDS.128.
// ---------------------------------------------------------------------------
template<int CIN,int COUT,int KW,int W,int COG,int NT,int TP,int INMODE,bool POOL>
__global__ void __launch_bounds__(NT) conv_bn_kernel(
    const float* __restrict__ in0, const float* __restrict__ in1,
    const float* __restrict__ wt,  const float* __restrict__ bias,
    float* __restrict__ out0, float* __restrict__ out1,
    const float* __restrict__ aff0, const float* __restrict__ aff1,
    float* __restrict__ sum0, float* __restrict__ sum1,
    float* __restrict__ sq0,  float* __restrict__ sq1)
{
    constexpr int TILE = NT * TP;
    constexpr int PAD  = (KW - 1) / 2;
    constexpr int XROW = TILE + KW - 1;
    constexpr int NCG  = COUT / COG;
    constexpr int CACC = 8;
    constexpr int KWP  = (KW + 3) & ~3;     // padded weight stride (float4 rows)
    constexpr int NXV  = TP + KW - 1;       // input window per thread
    constexpr bool VECX = (TP % 4 == 0) && (NXV % 4 == 0) && (XROW % 4 == 0);
    static_assert(COG % CACC == 0, "");
    static_assert(!POOL || TP == 4, "");

    extern __shared__ float sh[];
    float* sx   = sh;                       // CIN*XROW activated input tile
    float* sw   = sx + CIN * XROW;          // COG*CIN*KWP weights (padded)
    float* sb   = sw + COG * CIN * KWP;     // COG bias
    float* ssum = sb + COG;                 // COG block-partial sums
    float* ssq  = ssum + COG;               // COG block-partial sumsqs
    static_assert((CIN * XROW) % 4 == 0, "sw must stay 16B aligned");

    const int z      = blockIdx.z;
    const int stream = z / NCG;
    const int cg     = z - stream * NCG;
    const float* __restrict__ in  = stream ? in1  : in0;
    float*       __restrict__ out = stream ? out1 : out0;
    const float* __restrict__ af  = stream ? aff1 : aff0;
    float* gsum = stream ? sum1 : sum0;
    float* gsq  = stream ? sq1  : sq0;
    const int b     = blockIdx.y;
    const int tbase = blockIdx.x * TILE;
    const int tid   = threadIdx.x;

    for (int i = tid; i < COG; i += NT) { sb[i] = bias[cg*COG + i]; ssum[i] = 0.f; ssq[i] = 0.f; }
    for (int i = tid; i < COG*CIN*KWP; i += NT) {
        int co = i / (CIN*KWP);
        int r  = i - co*(CIN*KWP);
        int ci = r / KWP;
        int k  = r - ci*KWP;
        float v = 0.f;
        if (k < KW) v = wt[(cg*COG + co)*(CIN*KW) + ci*KW + k];
        sw[i] = v;
    }
    for (int i = tid; i < CIN*XROW; i += NT) {
        int ci = i / XROW;
        int p  = i - ci*XROW;
        int g  = tbase - PAD + p;
        float v = 0.f;
        if (g >= 0 && g < W) {
            if constexpr (INMODE == 0) {
                v = in[(b*CIN + ci)*W + g];
            } else if constexpr (INMODE == 1) {
                float a = af[ci*2+0], bb = af[ci*2+1];
                float2 mm = ((const float2*)in)[(b*CIN + ci)*W + g];
                v = fmaxf(fmaxf(fmaf(a, mm.x, bb), fmaf(a, mm.y, bb)), 0.f);
            } else {
                float a = af[ci*2+0], bb = af[ci*2+1];
                v = fmaxf(fmaf(a, in[(b*CIN + ci)*W + g], bb), 0.f);
            }
        }
        sx[i] = v;
    }
    __syncthreads();

    const int x0   = tid * TP;
    const int lane = tid & 31;

    #pragma unroll 1
    for (int ch = 0; ch < COG; ch += CACC) {
        float acc[CACC][TP];
        #pragma unroll
        for (int c = 0; c < CACC; c++)
            #pragma unroll
            for (int p = 0; p < TP; p++) acc[c][p] = sb[ch + c];

        #pragma unroll 1
        for (int ci = 0; ci < CIN; ci++) {
            float xv[NXV];
            if constexpr (VECX) {
                const float4* sxr4 = reinterpret_cast<const float4*>(sx + ci*XROW + x0);
                #pragma unroll
                for (int q = 0; q < NXV/4; q++) {
                    float4 t = sxr4[q];
                    xv[4*q+0] = t.x; xv[4*q+1] = t.y;
                    xv[4*q+2] = t.z; xv[4*q+3] = t.w;
                }
            } else {
                const float* sxr = sx + ci*XROW + x0;
                #pragma unroll
                for (int i2 = 0; i2 < NXV; i2++) xv[i2] = sxr[i2];
            }
            #pragma unroll
            for (int c = 0; c < CACC; c++) {
                const float4* swp = reinterpret_cast<const float4*>(
                    sw + ((ch + c)*CIN + ci)*KWP);
                #pragma unroll
                for (int kq = 0; kq < (KW + 3)/4; kq++) {
                    float4 w4 = swp[kq];
                    const int kb = 4*kq;
                    if (kb + 0 < KW) {
                        #pragma unroll
                        for (int p = 0; p < TP; p++)
                            acc[c][p] = fmaf(xv[kb + 0 + p], w4.x, acc[c][p]);
                    }
                    if (kb + 1 < KW) {
                        #pragma unroll
                        for (int p = 0; p < TP; p++)
                            acc[c][p] = fmaf(xv[kb + 1 + p], w4.y, acc[c][p]);
                    }
                    if (kb + 2 < KW) {
                        #pragma unroll
                        for (int p = 0; p < TP; p++)
                            acc[c][p] = fmaf(xv[kb + 2 + p], w4.z, acc[c][p]);
                    }
                    if (kb + 3 < KW) {
                        #pragma unroll
                        for (int p = 0; p < TP; p++)
                            acc[c][p] = fmaf(xv[kb + 3 + p], w4.w, acc[c][p]);
                    }
                }
            }
        }

        #pragma unroll
        for (int c = 0; c < CACC; c++) {
            float s = 0.f, s2 = 0.f;
            float mx = -3.4e38f, mn = 3.4e38f;
            #pragma unroll
            for (int p = 0; p < TP; p++) {
                float v = acc[c][p];
                s += v; s2 = fmaf(v, v, s2);
                mx = fmaxf(mx, v); mn = fminf(mn, v);
            }
            float rs = warpReduceSum(s);
            float rq = warpReduceSum(s2);
            if (lane == 0) { atomicAdd(&ssum[ch + c], rs); atomicAdd(&ssq[ch + c], rq); }
            const int coG = cg*COG + ch + c;
            if constexpr (POOL) {
                ((float2*)out)[(b*COUT + coG)*(W/4) + (tbase >> 2) + tid] = make_float2(mx, mn);
            } else {
                #pragma unroll
                for (int p = 0; p < TP; p++)
                    out[(b*COUT + coG)*W + tbase + x0 + p] = acc[c][p];
            }
        }
    }
    __syncthreads();
    for (int i = tid; i < COG; i += NT) {
        atomicAdd(&gsum[cg*COG + i], ssum[i]);
        atomicAdd(&gsq[cg*COG + i], ssq[i]);
    }
}

// ---------------------------------------------------------------------------
// small kernels
// ---------------------------------------------------------------------------
__global__ void zero_stats_kernel() {
    int i = blockIdx.x * blockDim.x + threadIdx.x;
    if (i < 2*5*64) { g_sum[i] = 0.f; g_sq[i] = 0.f; }
}

__global__ void finalize_bn_kernel(const float* __restrict__ gamma,
                                   const float* __restrict__ beta,
                                   int C, float invN, int stage) {
    int z = blockIdx.x; int c = threadIdx.x;
    if (c < C) {
        float s = g_sum[(z*5 + stage)*64 + c];
        float q = g_sq [(z*5 + stage)*64 + c];
        float mean = s * invN;
        float var  = fmaf(-mean, mean, q * invN);
        float a    = gamma[c] * rsqrtf(var + EPS_BN);
        float bb   = beta[c] - a * mean;
        g_aff[((z*5 + stage)*64 + c)*2 + 0] = a;
        g_aff[((z*5 + stage)*64 + c)*2 + 1] = bb;
    }
}

// h = relu(affine(stage2 pooled minmax))
__global__ void hcompute_kernel() {
    int z = blockIdx.y;
    int idx = blockIdx.x * blockDim.x + threadIdx.x;   // < 2097152
    const float* af = &g_aff[(z*5 + 2)*128];
    int c = (idx >> 7) & 63;
    float a = af[c*2], bb = af[c*2+1];
    float2 mm = ((const float2*)g_c3[z])[idx];
    g_h[z][idx] = fmaxf(fmaxf(fmaf(a, mm.x, bb), fmaf(a, mm.y, bb)), 0.f);
}

// per (stream,b,c): center+l2norm h row, emit 5 window sums S
__global__ void sprep_kernel() {
    int c = blockIdx.x, b = blockIdx.y, z = blockIdx.z;
    int t = threadIdx.x;                 // 128 threads
    __shared__ float scr[4];
    __shared__ float sedge[4];
    float v = g_h[z][(b*64 + c)*128 + t];
    float sum  = blockReduceSum(v, scr, 4);
    float mean = sum * (1.f/128.f);
    float e = v - mean;
    float q  = blockReduceSum(e*e, scr, 4);
    float se = blockReduceSum(e,   scr, 4);
    float inv = 1.f / fmaxf(sqrtf(q), EPS_NORM);
    float eh = e * inv;
    if (t == 0)   sedge[0] = eh;
    if (t == 1)   sedge[1] = eh;
    if (t == 126) sedge[2] = eh;
    if (t == 127) sedge[3] = eh;
    __syncthreads();
    if (t == 0) {
        float T = se * inv;
        float* o = &g_S[z][(b*64 + c)*5];
        o[0] = T - sedge[2] - sedge[3];
        o[1] = T - sedge[3];
        o[2] = T;
        o[3] = T - sedge[0];
        o[4] = T - sedge[0] - sedge[1];
    }
}

// per (stream,b): activate t2 raw (stage4 affine), adaptive-pool to 5 bins,
// emit flat-normalized k (320) and per-channel centered+normalized k (64x5).
__global__ void kcompute_kernel() {
    int b = blockIdx.x, z = blockIdx.y;
    int c = threadIdx.x;                 // 64 threads
    __shared__ float scr[2];
    const float* af = &g_aff[(z*5 + 4)*128];
    float a = af[c*2], bb = af[c*2+1];
    const float* row = &g_t2[z][(b*64 + c)*128];
    const int s0[5] = {0, 25, 51, 76, 102};
    const int e0[5] = {26, 52, 77, 103, 128};
    float kk[5];
    float local = 0.f;
    #pragma unroll
    for (int i = 0; i < 5; i++) {
        float s = 0.f;
        for (int w = s0[i]; w < e0[i]; w++)
            s += fmaxf(fmaf(a, row[w], bb), 0.f);
        kk[i] = s / (float)(e0[i] - s0[i]);
        local = fmaf(kk[i], kk[i], local);
    }
    float tot = blockReduceSum(local, scr, 2);
    float invf = 1.f / fmaxf(sqrtf(tot), EPS_NORM);
    float mu = (kk[0]+kk[1]+kk[2]+kk[3]+kk[4]) * 0.2f;
    float nn2 = 0.f;
    float d[5];
    #pragma unroll
    for (int i = 0; i < 5; i++) { d[i] = kk[i] - mu; nn2 = fmaf(d[i], d[i], nn2); }
    float invc = 1.f / fmaxf(sqrtf(nn2), EPS_NORM);
    #pragma unroll
    for (int i = 0; i < 5; i++) {
        g_ka[z][b*320 + c*5 + i]      = kk[i] * invf;
        g_kc[z][(b*64 + c)*5 + i]     = d[i] * invc;
    }
}

// three 256x256x320 GEMMs (A·B^T)
__global__ void matmul_kernel() {
    int m = blockIdx.z;
    const float* A; const float* Bm; float scale;
    if (m == 0)      { A = g_kc[0]; Bm = g_S[1];  scale = 1.f/128.f; }
    else if (m == 1) { A = g_kc[1]; Bm = g_S[0];  scale = 1.f/128.f; }
    else             { A = g_ka[0]; Bm = g_ka[1]; scale = 1.f; }
    __shared__ float As[16][33], Bs[16][33];
    int tx = threadIdx.x, ty = threadIdx.y;
    int i0 = blockIdx.x * 16, j0 = blockIdx.y * 16;
    float acc = 0.f;
    for (int kk = 0; kk < 320; kk += 32) {
        As[ty][tx]      = A [(i0+ty)*320 + kk + tx];
        As[ty][tx+16]   = A [(i0+ty)*320 + kk + tx + 16];
        Bs[ty][tx]      = Bm[(j0+ty)*320 + kk + tx];
        Bs[ty][tx+16]   = Bm[(j0+ty)*320 + kk + tx + 16];
        __syncthreads();
        #pragma unroll
        for (int k2 = 0; k2 < 32; k2++)
            acc = fmaf(As[ty][k2], Bs[tx][k2], acc);
        __syncthreads();
    }
    g_sim[m][(i0+ty)*256 + j0 + tx] = acc * scale;
}

// per-row infonce: logp diag = x_ii - logsumexp_j(x_ij), x = sim/T
__global__ void rows_kernel() {
    int i = blockIdx.x, m = blockIdx.y;
    int j = threadIdx.x;                 // 256
    __shared__ float scr[8];
    __shared__ float sdiag;
    float x = g_sim[m][i*256 + j] * 10.0f;     // 1/TEMPERATURE
    if (j == i) sdiag = x;
    float mx = blockReduceMax(x, scr, 8);
    float e  = expf(x - mx);
    float tot = blockReduceSum(e, scr, 8);
    if (j == 0) g_row[m*256 + i] = sdiag - (mx + logf(tot));
}

__global__ void final_kernel(float* out) {
    int t = threadIdx.x;                 // 256
    __shared__ float scr[8];
    float sA = blockReduceSum(g_row[0*256 + t], scr, 8);
    float sB = blockReduceSum(g_row[1*256 + t], scr, 8);
    float sC = blockReduceSum(g_row[2*256 + t], scr, 8);
    if (t == 0) {
        float mA = sA * (1.f/256.f);
        float mB = sB * (1.f/256.f);
        float mC = sC * (1.f/256.f);
        // loss_matching = (-mA + -mB)/2 ; loss_template = -mC
        out[0] = (-mA - mB) * 0.5f + 0.5f * (-mC);
    }
}

// ---------------------------------------------------------------------------
// host
// ---------------------------------------------------------------------------
extern "C" void kernel_launch(void* const* d_in, const int* in_sizes, int n_in,
                              void* d_out, int out_size) {
    (void)in_sizes; (void)n_in; (void)out_size;
    const float* x1  = (const float*)d_in[0];
    const float* x2  = (const float*)d_in[1];
    const float* w1  = (const float*)d_in[2];
    const float* b1  = (const float*)d_in[3];
    const float* g1  = (const float*)d_in[4];
    const float* be1 = (const float*)d_in[5];
    const float* w2  = (const float*)d_in[6];
    const float* b2  = (const float*)d_in[7];
    const float* g2  = (const float*)d_in[8];
    const float* be2 = (const float*)d_in[9];
    const float* w3  = (const float*)d_in[10];
    const float* b3  = (const float*)d_in[11];
    const float* g3  = (const float*)d_in[12];
    const float* be3 = (const float*)d_in[13];
    const float* tw1 = (const float*)d_in[14];
    const float* tb1 = (const float*)d_in[15];
    const float* tg1 = (const float*)d_in[16];
    const float* tbe1= (const float*)d_in[17];
    const float* tw2 = (const float*)d_in[18];
    const float* tb2 = (const float*)d_in[19];
    const float* tg2 = (const float*)d_in[20];
    const float* tbe2= (const float*)d_in[21];

    float *pc1, *pc2, *pc3, *ph, *pt1, *pt2, *psum, *psq, *paff;
    cudaGetSymbolAddress((void**)&pc1, g_c1);
    cudaGetSymbolAddress((void**)&pc2, g_c2);
    cudaGetSymbolAddress((void**)&pc3, g_c3);
    cudaGetSymbolAddress((void**)&ph,  g_h);
    cudaGetSymbolAddress((void**)&pt1, g_t1);
    cudaGetSymbolAddress((void**)&pt2, g_t2);
    cudaGetSymbolAddress((void**)&psum, g_sum);
    cudaGetSymbolAddress((void**)&psq,  g_sq);
    cudaGetSymbolAddress((void**)&paff, g_aff);

    const int S_C1 = 16777216, S_C2 = 8388608, S_C3 = 4194304, S_H = 2097152;
    auto SUMP = [&](int z, int st) { return psum + (z*5 + st)*64; };
    auto SQP  = [&](int z, int st) { return psq  + (z*5 + st)*64; };
    auto AFFP = [&](int z, int st) { return paff + (z*5 + st)*128; };

    auto kc1 = conv_bn_kernel<1, 16, 17, 8192, 16, 256, 4, 0, true >;
    auto kc2 = conv_bn_kernel<16,32, 17, 2048, 32, 128, 4, 1, true >;
    auto kc3 = conv_bn_kernel<32,64, 17, 512,  16, 128, 4, 1, true >;
    auto kt1 = conv_bn_kernel<64,64, 5,  128,  16, 64,  2, 0, false>;
    auto kt2 = conv_bn_kernel<64,64, 3,  128,  16, 64,  2, 2, false>;

    // smem sizes: (CIN*XROW + COG*CIN*KWP + 3*COG) * 4
    const int sm_c1 = (1*1040  + 16*1*20  + 3*16)*4;   // 5632
    const int sm_c2 = (16*528  + 32*16*20 + 3*32)*4;   // 75136
    const int sm_c3 = (32*528  + 16*32*20 + 3*16)*4;   // 108736
    const int sm_t1x= (64*132  + 16*64*8  + 3*16)*4;   // 66752
    const int sm_t2 = (64*130  + 16*64*4  + 3*16)*4;   // 49856

    cudaFuncSetAttribute((const void*)kc2, cudaFuncAttributeMaxDynamicSharedMemorySize, sm_c2);
    cudaFuncSetAttribute((const void*)kc3, cudaFuncAttributeMaxDynamicSharedMemorySize, sm_c3);
    cudaFuncSetAttribute((const void*)kt1, cudaFuncAttributeMaxDynamicSharedMemorySize, sm_t1x);
    cudaFuncSetAttribute((const void*)kt2, cudaFuncAttributeMaxDynamicSharedMemorySize, sm_t2);

    zero_stats_kernel<<<3, 256>>>();

    // stage 0: conv1 + stats + pooled minmax
    kc1<<<dim3(8, BB, 2), 256, sm_c1>>>(x1, x2, w1, b1,
        pc1, pc1 + S_C1, nullptr, nullptr,
        SUMP(0,0), SUMP(1,0), SQP(0,0), SQP(1,0));
    finalize_bn_kernel<<<2, 64>>>(g1, be1, 16, 1.f/(256.f*8192.f), 0);

    // stage 1: conv2
    kc2<<<dim3(4, BB, 2), 128, sm_c2>>>(pc1, pc1 + S_C1, w2, b2,
        pc2, pc2 + S_C2, AFFP(0,0), AFFP(1,0),
        SUMP(0,1), SUMP(1,1), SQP(0,1), SQP(1,1));
    finalize_bn_kernel<<<2, 64>>>(g2, be2, 32, 1.f/(256.f*2048.f), 1);

    // stage 2: conv3 (4 cogroups per stream)
    kc3<<<dim3(1, BB, 8), 128, sm_c3>>>(pc2, pc2 + S_C2, w3, b3,
        pc3, pc3 + S_C3, AFFP(0,1), AFFP(1,1),
        SUMP(0,2), SUMP(1,2), SQP(0,2), SQP(1,2));
    finalize_bn_kernel<<<2, 64>>>(g3, be3, 64, 1.f/(256.f*512.f), 2);

    // encoder output h
    hcompute_kernel<<<dim3(8192, 2), 256>>>();

    // template head conv1 (input = h, raw)
    kt1<<<dim3(1, BB, 8), 64, sm_t1x>>>(ph, ph + S_H, tw1, tb1,
        pt1, pt1 + S_H, nullptr, nullptr,
        SUMP(0,3), SUMP(1,3), SQP(0,3), SQP(1,3));
    finalize_bn_kernel<<<2, 64>>>(tg1, tbe1, 64, 1.f/(256.f*128.f), 3);

    // template head conv2 (input = t1 raw + stage3 affine + relu)
    kt2<<<dim3(1, BB, 8), 64, sm_t2>>>(pt1, pt1 + S_H, tw2, tb2,
        pt2, pt2 + S_H, AFFP(0,3), AFFP(1,3),
        SUMP(0,4), SUMP(1,4), SQP(0,4), SQP(1,4));
    finalize_bn_kernel<<<2, 64>>>(tg2, tbe2, 64, 1.f/(256.f*128.f), 4);

    // heads + similarity + losses
    kcompute_kernel<<<dim3(256, 2), 64>>>();
    sprep_kernel<<<dim3(64, 256, 2), 128>>>();
    matmul_kernel<<<dim3(16, 16, 3), dim3(16, 16)>>>();
    rows_kernel<<<dim3(256, 3), 256>>>();
    final_kernel<<<1, 256>>>((float*)d_out);
}

// round 15
// speedup vs baseline: 1.1600x; 1.0661x over previous
#include <cuda_runtime.h>
#include <math.h>

// ---------------------------------------------------------------------------
// TCCLModel — full pipeline on GB300, fp32, multi-kernel (BN batch stats need
// global syncs). All scratch in __device__ globals (no allocation anywhere).
// R5: packed f32x2 FMA (fma.rn.f32x2) in conv inner loop, channel-pair packed
// accumulators, weights stored co-innermost in smem so LDS.128 yields two
// packed weight pairs directly. 2x fp32 FMA throughput vs scalar FFMA.
// ---------------------------------------------------------------------------

#define EPS_BN   1e-5f
#define EPS_NORM 1e-12f

// dims
#define BB   256
#define LL   8192

// scratch (per stream: 0 = x1 path, 1 = x2 path)
// pooled raw conv outputs stored as (max,min) pairs: layout [b][c][wp][2]
static __device__ float g_c1[2][16777216];  // 256*16*2048*2
static __device__ float g_c2[2][8388608];   // 256*32*512*2
static __device__ float g_c3[2][4194304];   // 256*64*128*2
static __device__ float g_h [2][2097152];   // 256*64*128  (encoder output h)
static __device__ float g_t1[2][2097152];   // tconv1 raw
static __device__ float g_t2[2][2097152];   // tconv2 raw
static __device__ float g_S [2][81920];     // 256*64*5 window sums of normalized h
static __device__ float g_kc[2][81920];     // 256*64*5 centered+normalized k
static __device__ float g_ka[2][81920];     // 256*320 flat-normalized k
static __device__ float g_sum[2*5*64];      // BN sums   [stream][stage][ch]
static __device__ float g_sq [2*5*64];      // BN sumsqs
static __device__ float g_aff[2*5*64*2];    // BN affine (a,b) per channel
static __device__ float g_sim[3][65536];    // three 256x256 similarity matrices
static __device__ float g_row[3*256];       // per-row infonce terms

// ---------------------------------------------------------------------------
// packed f32x2 helpers (ptxas never auto-emits FFMA2 — PTX only)
// ---------------------------------------------------------------------------
static __device__ __forceinline__ unsigned long long pack2(float lo, float hi) {
    unsigned long long r;
    asm("mov.b64 %0, {%1, %2};" : "=l"(r) : "f"(lo), "f"(hi));
    return r;
}
static __device__ __forceinline__ void unpack2(unsigned long long v, float& lo, float& hi) {
    asm("mov.b64 {%0, %1}, %2;" : "=f"(lo), "=f"(hi) : "l"(v));
}
static __device__ __forceinline__ unsigned long long ffma2(
    unsigned long long a, unsigned long long b, unsigned long long c) {
    unsigned long long d;
    asm("fma.rn.f32x2 %0, %1, %2, %3;" : "=l"(d) : "l"(a), "l"(b), "l"(c));
    return d;
}

// ---------------------------------------------------------------------------
// reductions
// ---------------------------------------------------------------------------
static __device__ __forceinline__ float warpReduceSum(float v) {
    #pragma unroll
    for (int o = 16; o > 0; o >>= 1) v += __shfl_xor_sync(0xffffffffu, v, o);
    return v;
}
static __device__ __forceinline__ float warpReduceMax(float v) {
    #pragma unroll
    for (int o = 16; o > 0; o >>= 1) v = fmaxf(v, __shfl_xor_sync(0xffffffffu, v, o));
    return v;
}
static __device__ __forceinline__ float blockReduceSum(float v, float* scr, int nw) {
    int tid = threadIdx.x;
    v = warpReduceSum(v);
    if ((tid & 31) == 0) scr[tid >> 5] = v;
    __syncthreads();
    float r = 0.f;
    for (int i = 0; i < nw; i++) r += scr[i];
    __syncthreads();
    return r;
}
static __device__ __forceinline__ float blockReduceMax(float v, float* scr, int nw) {
    int tid = threadIdx.x;
    v = warpReduceMax(v);
    if ((tid & 31) == 0) scr[tid >> 5] = v;
    __syncthreads();
    float r = -3.4e38f;
    for (int i = 0; i < nw; i++) r = fmaxf(r, scr[i]);
    __syncthreads();
    return r;
}

// ---------------------------------------------------------------------------
// generic fused conv1d('same') + raw-stat accumulation (+ optional pooled
// min/max output).  INMODE: 0 = raw input, 1 = (max,min)+affine+relu,
// 2 = raw+affine+relu.  POOL: write (max,min) over aligned 4-windows.
// Register blocking: CACC=8 output channels (4 f32x2 pairs) x TP positions.
// Weights in smem co-innermost: sw[(ci*KWP + k)*COG + co]; a single LDS.128
// fetches 4 consecutive co = two packed f32x2 weight pairs, no pack instrs.
// ---------------------------------------------------------------------------
template<int CIN,int COUT,int KW,int W,int COG,int NT,int TP,int INMODE,bool POOL>
__global__ void __launch_bounds__(NT) conv_bn_kernel(
    const float* __restrict__ in0, const float* __restrict__ in1,
    const float* __restrict__ wt,  const float* __restrict__ bias,
    float* __restrict__ out0, float* __restrict__ out1,
    const float* __restrict__ aff0, const float* __restrict__ aff1,
    float* __restrict__ sum0, float* __restrict__ sum1,
    float* __restrict__ sq0,  float* __restrict__ sq1)
{
    constexpr int TILE = NT * TP;
    constexpr int PAD  = (KW - 1) / 2;
    constexpr int XROW = TILE + KW - 1;
    constexpr int NCG  = COUT / COG;
    constexpr int CACC = 8;
    constexpr int NCP  = CACC / 2;          // channel pairs
    constexpr int KWP  = (KW + 3) & ~3;     // padded k-extent
    constexpr int NXV  = TP + KW - 1;       // input window per thread
    constexpr bool VECX = (TP % 4 == 0) && (NXV % 4 == 0) && (XROW % 4 == 0);
    static_assert(COG % CACC == 0, "");
    static_assert(COG % 4 == 0, "");
    static_assert(!POOL || TP == 4, "");

    extern __shared__ float sh[];
    float* sx   = sh;                       // CIN*XROW activated input tile
    float* sw   = sx + CIN * XROW;          // CIN*KWP*COG weights (co innermost)
    float* sb   = sw + CIN * KWP * COG;     // COG bias
    float* ssum = sb + COG;                 // COG block-partial sums
    float* ssq  = ssum + COG;               // COG block-partial sumsqs
    static_assert((CIN * XROW) % 4 == 0, "sw must stay 16B aligned");

    const int z      = blockIdx.z;
    const int stream = z / NCG;
    const int cg     = z - stream * NCG;
    const float* __restrict__ in  = stream ? in1  : in0;
    float*       __restrict__ out = stream ? out1 : out0;
    const float* __restrict__ af  = stream ? aff1 : aff0;
    float* gsum = stream ? sum1 : sum0;
    float* gsq  = stream ? sq1  : sq0;
    const int b     = blockIdx.y;
    const int tbase = blockIdx.x * TILE;
    const int tid   = threadIdx.x;

    for (int i = tid; i < COG; i += NT) { sb[i] = bias[cg*COG + i]; ssum[i] = 0.f; ssq[i] = 0.f; }
    for (int i = tid; i < CIN*KWP*COG; i += NT) {
        // layout: ((ci*KWP + k)*COG + co)
        int ci = i / (KWP*COG);
        int r  = i - ci*(KWP*COG);
        int k  = r / COG;
        int co = r - k*COG;
        float v = 0.f;
        if (k < KW) v = wt[(cg*COG + co)*(CIN*KW) + ci*KW + k];
        sw[i] = v;
    }
    for (int i = tid; i < CIN*XROW; i += NT) {
        int ci = i / XROW;
        int p  = i - ci*XROW;
        int g  = tbase - PAD + p;
        float v = 0.f;
        if (g >= 0 && g < W) {
            if constexpr (INMODE == 0) {
                v = in[(b*CIN + ci)*W + g];
            } else if constexpr (INMODE == 1) {
                float a = af[ci*2+0], bb = af[ci*2+1];
                float2 mm = ((const float2*)in)[(b*CIN + ci)*W + g];
                v = fmaxf(fmaxf(fmaf(a, mm.x, bb), fmaf(a, mm.y, bb)), 0.f);
            } else {
                float a = af[ci*2+0], bb = af[ci*2+1];
                v = fmaxf(fmaf(a, in[(b*CIN + ci)*W + g], bb), 0.f);
            }
        }
        sx[i] = v;
    }
    __syncthreads();

    const int x0   = tid * TP;
    const int lane = tid & 31;

    #pragma unroll 1
    for (int ch = 0; ch < COG; ch += CACC) {
        unsigned long long acc2[NCP][TP];
        #pragma unroll
        for (int cp = 0; cp < NCP; cp++) {
            unsigned long long b2 = pack2(sb[ch + 2*cp], sb[ch + 2*cp + 1]);
            #pragma unroll
            for (int p = 0; p < TP; p++) acc2[cp][p] = b2;
        }

        #pragma unroll 1
        for (int ci = 0; ci < CIN; ci++) {
            float xv[NXV];
            if constexpr (VECX) {
                const float4* sxr4 = reinterpret_cast<const float4*>(sx + ci*XROW + x0);
                #pragma unroll
                for (int q = 0; q < NXV/4; q++) {
                    float4 t = sxr4[q];
                    xv[4*q+0] = t.x; xv[4*q+1] = t.y;
                    xv[4*q+2] = t.z; xv[4*q+3] = t.w;
                }
            } else {
                const float* sxr = sx + ci*XROW + x0;
                #pragma unroll
                for (int i2 = 0; i2 < NXV; i2++) xv[i2] = sxr[i2];
            }
            unsigned long long xb[NXV];
            #pragma unroll
            for (int i2 = 0; i2 < NXV; i2++) xb[i2] = pack2(xv[i2], xv[i2]);

            #pragma unroll
            for (int k = 0; k < KW; k++) {
                const ulonglong2* wrow = reinterpret_cast<const ulonglong2*>(
                    sw + (ci*KWP + k)*COG + ch);
                ulonglong2 wA = wrow[0];
                ulonglong2 wB = wrow[1];
                unsigned long long wp[NCP] = {wA.x, wA.y, wB.x, wB.y};
                #pragma unroll
                for (int cp = 0; cp < NCP; cp++) {
                    #pragma unroll
                    for (int p = 0; p < TP; p++)
                        acc2[cp][p] = ffma2(xb[k + p], wp[cp], acc2[cp][p]);
                }
            }
        }

        float acc[CACC][TP];
        #pragma unroll
        for (int cp = 0; cp < NCP; cp++)
            #pragma unroll
            for (int p = 0; p < TP; p++)
                unpack2(acc2[cp][p], acc[2*cp][p], acc[2*cp+1][p]);

        #pragma unroll
        for (int c = 0; c < CACC; c++) {
            float s = 0.f, s2 = 0.f;
            float mx = -3.4e38f, mn = 3.4e38f;
            #pragma unroll
            for (int p = 0; p < TP; p++) {
                float v = acc[c][p];
                s += v; s2 = fmaf(v, v, s2);
                mx = fmaxf(mx, v); mn = fminf(mn, v);
            }
            float rs = warpReduceSum(s);
            float rq = warpReduceSum(s2);
            if (lane == 0) { atomicAdd(&ssum[ch + c], rs); atomicAdd(&ssq[ch + c], rq); }
            const int coG = cg*COG + ch + c;
            if constexpr (POOL) {
                ((float2*)out)[(b*COUT + coG)*(W/4) + (tbase >> 2) + tid] = make_float2(mx, mn);
            } else {
                #pragma unroll
                for (int p = 0; p < TP; p++)
                    out[(b*COUT + coG)*W + tbase + x0 + p] = acc[c][p];
            }
        }
    }
    __syncthreads();
    for (int i = tid; i < COG; i += NT) {
        atomicAdd(&gsum[cg*COG + i], ssum[i]);
        atomicAdd(&gsq[cg*COG + i], ssq[i]);
    }
}

// ---------------------------------------------------------------------------
// small kernels
// ---------------------------------------------------------------------------
__global__ void zero_stats_kernel() {
    int i = blockIdx.x * blockDim.x + threadIdx.x;
    if (i < 2*5*64) { g_sum[i] = 0.f; g_sq[i] = 0.f; }
}

__global__ void finalize_bn_kernel(const float* __restrict__ gamma,
                                   const float* __restrict__ beta,
                                   int C, float invN, int stage) {
    int z = blockIdx.x; int c = threadIdx.x;
    if (c < C) {
        float s = g_sum[(z*5 + stage)*64 + c];
        float q = g_sq [(z*5 + stage)*64 + c];
        float mean = s * invN;
        float var  = fmaf(-mean, mean, q * invN);
        float a    = gamma[c] * rsqrtf(var + EPS_BN);
        float bb   = beta[c] - a * mean;
        g_aff[((z*5 + stage)*64 + c)*2 + 0] = a;
        g_aff[((z*5 + stage)*64 + c)*2 + 1] = bb;
    }
}

// h = relu(affine(stage2 pooled minmax))
__global__ void hcompute_kernel() {
    int z = blockIdx.y;
    int idx = blockIdx.x * blockDim.x + threadIdx.x;   // < 2097152
    const float* af = &g_aff[(z*5 + 2)*128];
    int c = (idx >> 7) & 63;
    float a = af[c*2], bb = af[c*2+1];
    float2 mm = ((const float2*)g_c3[z])[idx];
    g_h[z][idx] = fmaxf(fmaxf(fmaf(a, mm.x, bb), fmaf(a, mm.y, bb)), 0.f);
}

// per (stream,b,c): center+l2norm h row, emit 5 window sums S
__global__ void sprep_kernel() {
    int c = blockIdx.x, b = blockIdx.y, z = blockIdx.z;
    int t = threadIdx.x;                 // 128 threads
    __shared__ float scr[4];
    __shared__ float sedge[4];
    float v = g_h[z][(b*64 + c)*128 + t];
    float sum  = blockReduceSum(v, scr, 4);
    float mean = sum * (1.f/128.f);
    float e = v - mean;
    float q  = blockReduceSum(e*e, scr, 4);
    float se = blockReduceSum(e,   scr, 4);
    float inv = 1.f / fmaxf(sqrtf(q), EPS_NORM);
    float eh = e * inv;
    if (t == 0)   sedge[0] = eh;
    if (t == 1)   sedge[1] = eh;
    if (t == 126) sedge[2] = eh;
    if (t == 127) sedge[3] = eh;
    __syncthreads();
    if (t == 0) {
        float T = se * inv;
        float* o = &g_S[z][(b*64 + c)*5];
        o[0] = T - sedge[2] - sedge[3];
        o[1] = T - sedge[3];
        o[2] = T;
        o[3] = T - sedge[0];
        o[4] = T - sedge[0] - sedge[1];
    }
}

// per (stream,b): activate t2 raw (stage4 affine), adaptive-pool to 5 bins,
// emit flat-normalized k (320) and per-channel centered+normalized k (64x5).
__global__ void kcompute_kernel() {
    int b = blockIdx.x, z = blockIdx.y;
    int c = threadIdx.x;                 // 64 threads
    __shared__ float scr[2];
    const float* af = &g_aff[(z*5 + 4)*128];
    float a = af[c*2], bb = af[c*2+1];
    const float* row = &g_t2[z][(b*64 + c)*128];
    const int s0[5] = {0, 25, 51, 76, 102};
    const int e0[5] = {26, 52, 77, 103, 128};
    float kk[5];
    float local = 0.f;
    #pragma unroll
    for (int i = 0; i < 5; i++) {
        float s = 0.f;
        for (int w = s0[i]; w < e0[i]; w++)
            s += fmaxf(fmaf(a, row[w], bb), 0.f);
        kk[i] = s / (float)(e0[i] - s0[i]);
        local = fmaf(kk[i], kk[i], local);
    }
    float tot = blockReduceSum(local, scr, 2);
    float invf = 1.f / fmaxf(sqrtf(tot), EPS_NORM);
    float mu = (kk[0]+kk[1]+kk[2]+kk[3]+kk[4]) * 0.2f;
    float nn2 = 0.f;
    float d[5];
    #pragma unroll
    for (int i = 0; i < 5; i++) { d[i] = kk[i] - mu; nn2 = fmaf(d[i], d[i], nn2); }
    float invc = 1.f / fmaxf(sqrtf(nn2), EPS_NORM);
    #pragma unroll
    for (int i = 0; i < 5; i++) {
        g_ka[z][b*320 + c*5 + i]      = kk[i] * invf;
        g_kc[z][(b*64 + c)*5 + i]     = d[i] * invc;
    }
}

// three 256x256x320 GEMMs (A·B^T)
__global__ void matmul_kernel() {
    int m = blockIdx.z;
    const float* A; const float* Bm; float scale;
    if (m == 0)      { A = g_kc[0]; Bm = g_S[1];  scale = 1.f/128.f; }
    else if (m == 1) { A = g_kc[1]; Bm = g_S[0];  scale = 1.f/128.f; }
    else             { A = g_ka[0]; Bm = g_ka[1]; scale = 1.f; }
    __shared__ float As[16][33], Bs[16][33];
    int tx = threadIdx.x, ty = threadIdx.y;
    int i0 = blockIdx.x * 16, j0 = blockIdx.y * 16;
    float acc = 0.f;
    for (int kk = 0; kk < 320; kk += 32) {
        As[ty][tx]      = A [(i0+ty)*320 + kk + tx];
        As[ty][tx+16]   = A [(i0+ty)*320 + kk + tx + 16];
        Bs[ty][tx]      = Bm[(j0+ty)*320 + kk + tx];
        Bs[ty][tx+16]   = Bm[(j0+ty)*320 + kk + tx + 16];
        __syncthreads();
        #pragma unroll
        for (int k2 = 0; k2 < 32; k2++)
            acc = fmaf(As[ty][k2], Bs[tx][k2], acc);
        __syncthreads();
    }
    g_sim[m][(i0+ty)*256 + j0 + tx] = acc * scale;
}

// per-row infonce: logp diag = x_ii - logsumexp_j(x_ij), x = sim/T
__global__ void rows_kernel() {
    int i = blockIdx.x, m = blockIdx.y;
    int j = threadIdx.x;                 // 256
    __shared__ float scr[8];
    __shared__ float sdiag;
    float x = g_sim[m][i*256 + j] * 10.0f;     // 1/TEMPERATURE
    if (j == i) sdiag = x;
    float mx = blockReduceMax(x, scr, 8);
    float e  = expf(x - mx);
    float tot = blockReduceSum(e, scr, 8);
    if (j == 0) g_row[m*256 + i] = sdiag - (mx + logf(tot));
}

__global__ void final_kernel(float* out) {
    int t = threadIdx.x;                 // 256
    __shared__ float scr[8];
    float sA = blockReduceSum(g_row[0*256 + t], scr, 8);
    float sB = blockReduceSum(g_row[1*256 + t], scr, 8);
    float sC = blockReduceSum(g_row[2*256 + t], scr, 8);
    if (t == 0) {
        float mA = sA * (1.f/256.f);
        float mB = sB * (1.f/256.f);
        float mC = sC * (1.f/256.f);
        // loss_matching = (-mA + -mB)/2 ; loss_template = -mC
        out[0] = (-mA - mB) * 0.5f + 0.5f * (-mC);
    }
}

// ---------------------------------------------------------------------------
// host
// ---------------------------------------------------------------------------
extern "C" void kernel_launch(void* const* d_in, const int* in_sizes, int n_in,
                              void* d_out, int out_size) {
    (void)in_sizes; (void)n_in; (void)out_size;
    const float* x1  = (const float*)d_in[0];
    const float* x2  = (const float*)d_in[1];
    const float* w1  = (const float*)d_in[2];
    const float* b1  = (const float*)d_in[3];
    const float* g1  = (const float*)d_in[4];
    const float* be1 = (const float*)d_in[5];
    const float* w2  = (const float*)d_in[6];
    const float* b2  = (const float*)d_in[7];
    const float* g2  = (const float*)d_in[8];
    const float* be2 = (const float*)d_in[9];
    const float* w3  = (const float*)d_in[10];
    const float* b3  = (const float*)d_in[11];
    const float* g3  = (const float*)d_in[12];
    const float* be3 = (const float*)d_in[13];
    const float* tw1 = (const float*)d_in[14];
    const float* tb1 = (const float*)d_in[15];
    const float* tg1 = (const float*)d_in[16];
    const float* tbe1= (const float*)d_in[17];
    const float* tw2 = (const float*)d_in[18];
    const float* tb2 = (const float*)d_in[19];
    const float* tg2 = (const float*)d_in[20];
    const float* tbe2= (const float*)d_in[21];

    float *pc1, *pc2, *pc3, *ph, *pt1, *pt2, *psum, *psq, *paff;
    cudaGetSymbolAddress((void**)&pc1, g_c1);
    cudaGetSymbolAddress((void**)&pc2, g_c2);
    cudaGetSymbolAddress((void**)&pc3, g_c3);
    cudaGetSymbolAddress((void**)&ph,  g_h);
    cudaGetSymbolAddress((void**)&pt1, g_t1);
    cudaGetSymbolAddress((void**)&pt2, g_t2);
    cudaGetSymbolAddress((void**)&psum, g_sum);
    cudaGetSymbolAddress((void**)&psq,  g_sq);
    cudaGetSymbolAddress((void**)&paff, g_aff);

    const int S_C1 = 16777216, S_C2 = 8388608, S_C3 = 4194304, S_H = 2097152;
    auto SUMP = [&](int z, int st) { return psum + (z*5 + st)*64; };
    auto SQP  = [&](int z, int st) { return psq  + (z*5 + st)*64; };
    auto AFFP = [&](int z, int st) { return paff + (z*5 + st)*128; };

    auto kc1 = conv_bn_kernel<1, 16, 17, 8192, 16, 256, 4, 0, true >;
    auto kc2 = conv_bn_kernel<16,32, 17, 2048, 32, 128, 4, 1, true >;
    auto kc3 = conv_bn_kernel<32,64, 17, 512,  16, 128, 4, 1, true >;
    auto kt1 = conv_bn_kernel<64,64, 5,  128,  16, 64,  2, 0, false>;
    auto kt2 = conv_bn_kernel<64,64, 3,  128,  16, 64,  2, 2, false>;

    // smem sizes: (CIN*XROW + CIN*KWP*COG + 3*COG) * 4
    const int sm_c1 = (1*1040  + 1*20*16  + 3*16)*4;   // 5632
    const int sm_c2 = (16*528  + 16*20*32 + 3*32)*4;   // 75136
    const int sm_c3 = (32*528  + 32*20*16 + 3*16)*4;   // 108736
    const int sm_t1 = (64*132  + 64*8*16  + 3*16)*4;   // 66752
    const int sm_t2 = (64*130  + 64*4*16  + 3*16)*4;   // 49856

    cudaFuncSetAttribute((const void*)kc2, cudaFuncAttributeMaxDynamicSharedMemorySize, sm_c2);
    cudaFuncSetAttribute((const void*)kc3, cudaFuncAttributeMaxDynamicSharedMemorySize, sm_c3);
    cudaFuncSetAttribute((const void*)kt1, cudaFuncAttributeMaxDynamicSharedMemorySize, sm_t1);
    cudaFuncSetAttribute((const void*)kt2, cudaFuncAttributeMaxDynamicSharedMemorySize, sm_t2);

    zero_stats_kernel<<<3, 256>>>();

    // stage 0: conv1 + stats + pooled minmax
    kc1<<<dim3(8, BB, 2), 256, sm_c1>>>(x1, x2, w1, b1,
        pc1, pc1 + S_C1, nullptr, nullptr,
        SUMP(0,0), SUMP(1,0), SQP(0,0), SQP(1,0));
    finalize_bn_kernel<<<2, 64>>>(g1, be1, 16, 1.f/(256.f*8192.f), 0);

    // stage 1: conv2
    kc2<<<dim3(4, BB, 2), 128, sm_c2>>>(pc1, pc1 + S_C1, w2, b2,
        pc2, pc2 + S_C2, AFFP(0,0), AFFP(1,0),
        SUMP(0,1), SUMP(1,1), SQP(0,1), SQP(1,1));
    finalize_bn_kernel<<<2, 64>>>(g2, be2, 32, 1.f/(256.f*2048.f), 1);

    // stage 2: conv3 (4 cogroups per stream)
    kc3<<<dim3(1, BB, 8), 128, sm_c3>>>(pc2, pc2 + S_C2, w3, b3,
        pc3, pc3 + S_C3, AFFP(0,1), AFFP(1,1),
        SUMP(0,2), SUMP(1,2), SQP(0,2), SQP(1,2));
    finalize_bn_kernel<<<2, 64>>>(g3, be3, 64, 1.f/(256.f*512.f), 2);

    // encoder output h
    hcompute_kernel<<<dim3(8192, 2), 256>>>();

    // template head conv1 (input = h, raw)
    kt1<<<dim3(1, BB, 8), 64, sm_t1>>>(ph, ph + S_H, tw1, tb1,
        pt1, pt1 + S_H, nullptr, nullptr,
        SUMP(0,3), SUMP(1,3), SQP(0,3), SQP(1,3));
    finalize_bn_kernel<<<2, 64>>>(tg1, tbe1, 64, 1.f/(256.f*128.f), 3);

    // template head conv2 (input = t1 raw + stage3 affine + relu)
    kt2<<<dim3(1, BB, 8), 64, sm_t2>>>(pt1, pt1 + S_H, tw2, tb2,
        pt2, pt2 + S_H, AFFP(0,3), AFFP(1,3),
        SUMP(0,4), SUMP(1,4), SQP(0,4), SQP(1,4));
    finalize_bn_kernel<<<2, 64>>>(tg2, tbe2, 64, 1.f/(256.f*128.f), 4);

    // heads + similarity + losses
    kcompute_kernel<<<dim3(256, 2), 64>>>();
    sprep_kernel<<<dim3(64, 256, 2), 128>>>();
    matmul_kernel<<<dim3(16, 16, 3), dim3(16, 16)>>>();
    rows_kernel<<<dim3(256, 3), 256>>>();
    final_kernel<<<1, 256>>>((float*)d_out);
}